// round 3
// baseline (speedup 1.0000x reference)
#include <cuda_runtime.h>
#include <cstdint>

#define NN 100000
#define INC 128
#define HIDC 256
#define OUTC 128

// ---------------- scratch (device globals; no allocation allowed) ----------
__device__ float g_msg1[(size_t)NN * INC];   // 51.2 MB
__device__ float g_deg[NN];
__device__ float g_rdeg[NN];
__device__ float g_h[(size_t)NN * HIDC];     // 102.4 MB
__device__ float g_p[(size_t)NN * OUTC];     // 51.2 MB
__device__ float g_msg2[(size_t)NN * OUTC];  // 51.2 MB
__device__ int   g_idx64;                    // 1 if edge_index is int64, 0 if int32

// Buffer selector: avoids cudaGetSymbolAddress entirely (device-side symbol refs).
__device__ __forceinline__ float* bufsel(int s, const float* ext) {
    switch (s) {
        case 1: return g_msg1;
        case 2: return g_h;
        case 3: return g_p;
        case 4: return g_msg2;
        case 5: return g_deg;
        default: return const_cast<float*>(ext);
    }
}

// ---------------- small helpers -------------------------------------------
__device__ __forceinline__ unsigned long long pack2(float f) {
    unsigned long long r;
    asm("mov.b64 %0, {%1, %1};" : "=l"(r) : "f"(f));
    return r;
}
__device__ __forceinline__ void ffma2(unsigned long long& d, unsigned long long a,
                                      unsigned long long b) {
    asm("fma.rn.f32x2 %0, %1, %2, %0;" : "+l"(d) : "l"(a), "l"(b));
}
__device__ __forceinline__ void unpack2(unsigned long long v, float& lo, float& hi) {
    asm("mov.b64 {%0, %1}, %2;" : "=f"(lo), "=f"(hi) : "l"(v));
}

// ---------------- dtype detection -----------------------------------------
// If edge_index is int64 (little-endian, all values in [0, N) < 2^31), every
// odd 32-bit word is zero. For int32 random indices, 64 consecutive zeros at
// odd positions is impossible in practice.
__global__ void detect_idx_kernel(const int* __restrict__ idx) {
    if (threadIdx.x == 0 && blockIdx.x == 0) {
        int allzero = 1;
        for (int i = 1; i < 128; i += 2)
            if (idx[i] != 0) { allzero = 0; break; }
        g_idx64 = allzero;
    }
}

// ---------------- zero ----------------------------------------------------
__global__ void zero_kernel(int sel, int n4) {
    float* p = bufsel(sel, nullptr);
    int i = blockIdx.x * blockDim.x + threadIdx.x;
    int stride = gridDim.x * blockDim.x;
    float4 z = make_float4(0.f, 0.f, 0.f, 0.f);
    for (; i < n4; i += stride) reinterpret_cast<float4*>(p)[i] = z;
}

// ---------------- edge scatter (warp per edge, 128 floats) ----------------
__global__ void scatter_kernel(int featSel, const float* __restrict__ featExt,
                               int msgSel, int countDeg,
                               const int* __restrict__ idx, int E) {
    const float* feat = bufsel(featSel, featExt);
    float* msg = bufsel(msgSel, nullptr);
    bool w64 = (g_idx64 != 0);
    int lane = threadIdx.x & 31;
    int warp = (blockIdx.x * blockDim.x + threadIdx.x) >> 5;
    int nw = (gridDim.x * blockDim.x) >> 5;
    for (int e = warp; e < E; e += nw) {
        int s, d;
        if (w64) {
            s = __ldg(&idx[2 * e]);
            d = __ldg(&idx[2 * (E + e)]);
        } else {
            s = __ldg(&idx[e]);
            d = __ldg(&idx[E + e]);
        }
        s = min(max(s, 0), NN - 1);
        d = min(max(d, 0), NN - 1);
        float4 v = *reinterpret_cast<const float4*>(feat + (size_t)s * 128 + lane * 4);
        float* o = msg + (size_t)d * 128 + lane * 4;
        atomicAdd(o + 0, v.x);
        atomicAdd(o + 1, v.y);
        atomicAdd(o + 2, v.z);
        atomicAdd(o + 3, v.w);
        if (countDeg && lane == 0) atomicAdd(&g_deg[d], 1.0f);
    }
}

__global__ void rdeg_kernel(int n) {
    int i = blockIdx.x * blockDim.x + threadIdx.x;
    if (i < n) g_rdeg[i] = 1.0f / fmaxf(g_deg[i], 1.0f);
}

// ---------------- GEMM: C[M,NTOT] = A @ B^T (+mean)(+bias)(+relu) ---------
// DUAL:  K=256 concat: k<128 -> A0(msg1, scaled by rdeg) x B0; k>=128 -> A1(x) x B1
// !DUAL: A0 is [M,KTOT], B0 is [NTOT,KTOT]
// MEANADD: epilogue adds g_msg2[m, n] * rdeg[m]
template <bool DUAL, bool RELU, bool MEANADD, int NTOT, int KTOT>
__global__ __launch_bounds__(256, 2)
void gemm_kernel(int aSel, const float* __restrict__ Aext,
                 const float* __restrict__ A1,
                 const float* __restrict__ B0w, const float* __restrict__ B1w,
                 const float* __restrict__ bias,
                 int cSel, float* __restrict__ Cext, int M) {
    constexpr int BM = 128, BN = 64, BK = 16;
    constexpr int LDA = DUAL ? 128 : KTOT;
    constexpr int LDB = DUAL ? 128 : KTOT;
    __shared__ __align__(16) float As[BK][BM];
    __shared__ __align__(16) float Bs[BK][BN];
    __shared__ float rd_s[BM];

    const float* A0 = bufsel(aSel, Aext);
    float* C = bufsel(cSel, Cext);

    int tid = threadIdx.x;
    int mBase = blockIdx.y * BM;
    int nBase = blockIdx.x * BN;

    if (DUAL) {
        if (tid < BM) {
            int m = min(mBase + tid, M - 1);
            rd_s[tid] = g_rdeg[m];
        }
        __syncthreads();
    }

    unsigned long long acc[4][4];
#pragma unroll
    for (int i = 0; i < 4; i++)
#pragma unroll
        for (int j = 0; j < 4; j++) acc[i][j] = 0ULL;

    int tx = tid & 15;   // N dim (16 x 4)
    int ty = tid >> 4;   // M dim (16 x 8-rows as 4 f32x2 pairs)

    for (int kk = 0; kk < KTOT; kk += BK) {
        const float* Ap;
        bool scale = false;
        if (DUAL) {
            if (kk < 128) { Ap = A0; scale = true; }
            else          { Ap = A1; }
        } else {
            Ap = A0;
        }
        int ko = DUAL ? (kk & 127) : kk;
#pragma unroll
        for (int i = 0; i < 2; i++) {
            int l = tid + i * 256;          // 0..511 float4 slots
            int r = l >> 2;                 // row 0..127
            int kc = (l & 3) << 2;          // k offset 0,4,8,12
            int m = min(mBase + r, M - 1);
            float4 v = *reinterpret_cast<const float4*>(Ap + (size_t)m * LDA + ko + kc);
            if (DUAL && scale) {
                float s = rd_s[r];
                v.x *= s; v.y *= s; v.z *= s; v.w *= s;
            }
            As[kc + 0][r] = v.x; As[kc + 1][r] = v.y;
            As[kc + 2][r] = v.z; As[kc + 3][r] = v.w;
        }
        {
            const float* Bp = (DUAL && kk >= 128) ? B1w : B0w;
            int n = tid >> 2;
            int kc = (tid & 3) << 2;
            float4 w = *reinterpret_cast<const float4*>(Bp + (size_t)(nBase + n) * LDB + ko + kc);
            Bs[kc + 0][n] = w.x; Bs[kc + 1][n] = w.y;
            Bs[kc + 2][n] = w.z; Bs[kc + 3][n] = w.w;
        }
        __syncthreads();

#pragma unroll
        for (int k = 0; k < BK; k++) {
            const ulonglong2* ap = reinterpret_cast<const ulonglong2*>(&As[k][ty * 8]);
            ulonglong2 u0 = ap[0], u1 = ap[1];
            unsigned long long av0 = u0.x, av1 = u0.y, av2 = u1.x, av3 = u1.y;
            float4 b4 = *reinterpret_cast<const float4*>(&Bs[k][tx * 4]);
            unsigned long long bp0 = pack2(b4.x), bp1 = pack2(b4.y);
            unsigned long long bp2 = pack2(b4.z), bp3 = pack2(b4.w);
            ffma2(acc[0][0], av0, bp0); ffma2(acc[0][1], av0, bp1);
            ffma2(acc[0][2], av0, bp2); ffma2(acc[0][3], av0, bp3);
            ffma2(acc[1][0], av1, bp0); ffma2(acc[1][1], av1, bp1);
            ffma2(acc[1][2], av1, bp2); ffma2(acc[1][3], av1, bp3);
            ffma2(acc[2][0], av2, bp0); ffma2(acc[2][1], av2, bp1);
            ffma2(acc[2][2], av2, bp2); ffma2(acc[2][3], av2, bp3);
            ffma2(acc[3][0], av3, bp0); ffma2(acc[3][1], av3, bp1);
            ffma2(acc[3][2], av3, bp2); ffma2(acc[3][3], av3, bp3);
        }
        __syncthreads();
    }

    // ---- epilogue
    int m0 = mBase + ty * 8;
    int n0 = nBase + tx * 4;
    float4 b4 = make_float4(0.f, 0.f, 0.f, 0.f);
    if (bias != nullptr) b4 = *reinterpret_cast<const float4*>(bias + n0);

#pragma unroll
    for (int i = 0; i < 4; i++) {
        int r0 = m0 + 2 * i, r1 = r0 + 1;
        float lo[4], hi[4];
#pragma unroll
        for (int j = 0; j < 4; j++) unpack2(acc[i][j], lo[j], hi[j]);
        float4 vlo = make_float4(lo[0] + b4.x, lo[1] + b4.y, lo[2] + b4.z, lo[3] + b4.w);
        float4 vhi = make_float4(hi[0] + b4.x, hi[1] + b4.y, hi[2] + b4.z, hi[3] + b4.w);
        if (MEANADD) {
            if (r0 < M) {
                float s = g_rdeg[r0];
                float4 m4 = *reinterpret_cast<const float4*>(g_msg2 + (size_t)r0 * NTOT + n0);
                vlo.x += m4.x * s; vlo.y += m4.y * s; vlo.z += m4.z * s; vlo.w += m4.w * s;
            }
            if (r1 < M) {
                float s = g_rdeg[r1];
                float4 m4 = *reinterpret_cast<const float4*>(g_msg2 + (size_t)r1 * NTOT + n0);
                vhi.x += m4.x * s; vhi.y += m4.y * s; vhi.z += m4.z * s; vhi.w += m4.w * s;
            }
        }
        if (RELU) {
            vlo.x = fmaxf(vlo.x, 0.f); vlo.y = fmaxf(vlo.y, 0.f);
            vlo.z = fmaxf(vlo.z, 0.f); vlo.w = fmaxf(vlo.w, 0.f);
            vhi.x = fmaxf(vhi.x, 0.f); vhi.y = fmaxf(vhi.y, 0.f);
            vhi.z = fmaxf(vhi.z, 0.f); vhi.w = fmaxf(vhi.w, 0.f);
        }
        if (r0 < M) *reinterpret_cast<float4*>(C + (size_t)r0 * NTOT + n0) = vlo;
        if (r1 < M) *reinterpret_cast<float4*>(C + (size_t)r1 * NTOT + n0) = vhi;
    }
}

// ---------------- launch --------------------------------------------------
extern "C" void kernel_launch(void* const* d_in, const int* in_sizes, int n_in,
                              void* d_out, int out_size) {
    const float* x      = (const float*)d_in[0];
    const int* ei       = (const int*)d_in[1];   // int32 or int64, auto-detected
    // d_in[2] = edge_attr (unused by reference)
    const float* W1l    = (const float*)d_in[3];
    const float* W1r    = (const float*)d_in[4];
    const float* b1     = (const float*)d_in[5];
    const float* W2l    = (const float*)d_in[6];
    const float* W2r    = (const float*)d_in[7];
    const float* b2     = (const float*)d_in[8];
    float* out          = (float*)d_out;

    int M = in_sizes[0] / INC;        // 100000
    int E = in_sizes[1] / 2;          // 1600000

    int mTiles = (M + 127) / 128;

    // 0) detect index dtype
    detect_idx_kernel<<<1, 32>>>(ei);

    // 1) zero accumulators  (sel: 1=msg1, 4=msg2, 5=deg)
    zero_kernel<<<2048, 256>>>(1, M * INC / 4);
    zero_kernel<<<2048, 256>>>(4, M * OUTC / 4);
    zero_kernel<<<256, 256>>>(5, M / 4);

    // 2) layer-1 scatter: msg1 += x[src] at dst ; deg count
    scatter_kernel<<<2368, 256>>>(0, x, 1, 1, ei, E);

    // 3) reciprocal degree
    rdeg_kernel<<<(M + 255) / 256, 256>>>(M);

    // 4) h = relu( (msg1*rdeg) @ W1l^T + x @ W1r^T + b1 )
    gemm_kernel<true, true, false, HIDC, 256><<<dim3(HIDC / 64, mTiles), 256>>>(
        1, nullptr, x, W1l, W1r, b1, 2, nullptr, M);

    // 5) p = h @ W2l^T   (project BEFORE scatter: 128-wide instead of 256-wide)
    gemm_kernel<false, false, false, OUTC, HIDC><<<dim3(OUTC / 64, mTiles), 256>>>(
        2, nullptr, nullptr, W2l, nullptr, nullptr, 3, nullptr, M);

    // 6) layer-2 scatter: msg2 += p[src] at dst
    scatter_kernel<<<2368, 256>>>(3, nullptr, 4, 0, ei, E);

    // 7) out = msg2*rdeg + h @ W2r^T + b2
    gemm_kernel<false, false, true, OUTC, HIDC><<<dim3(OUTC / 64, mTiles), 256>>>(
        2, nullptr, nullptr, W2r, nullptr, b2, 0, out, M);
}

// round 11
// speedup vs baseline: 1.0122x; 1.0122x over previous
#include <cuda_runtime.h>
#include <cstdint>

#define NN 100000
#define EE 1700000
#define INC 128
#define HIDC 256
#define OUTC 128

// ---------------- scratch (device globals; no allocation allowed) ----------
__device__ float g_msg1[(size_t)NN * INC];   // mean of x over in-neighbors
__device__ float g_rdeg[NN];
__device__ float g_h[(size_t)NN * HIDC];
__device__ float g_p[(size_t)NN * OUTC];
__device__ float g_msg2[(size_t)NN * OUTC];  // mean of p over in-neighbors
__device__ int   g_count[NN];
__device__ int   g_offs[NN + 1];
__device__ int   g_cursor[NN];
__device__ int   g_eidx[EE];
__device__ int   g_idx64;

// Buffer selector (device-side symbol refs; no cudaGetSymbolAddress).
__device__ __forceinline__ float* bufsel(int s, const float* ext) {
    switch (s) {
        case 1: return g_msg1;
        case 2: return g_h;
        case 3: return g_p;
        case 4: return g_msg2;
        default: return const_cast<float*>(ext);
    }
}

// ---------------- f32x2 helpers -------------------------------------------
__device__ __forceinline__ unsigned long long pack2(float f) {
    unsigned long long r;
    asm("mov.b64 %0, {%1, %1};" : "=l"(r) : "f"(f));
    return r;
}
__device__ __forceinline__ void ffma2(unsigned long long& d, unsigned long long a,
                                      unsigned long long b) {
    asm("fma.rn.f32x2 %0, %1, %2, %0;" : "+l"(d) : "l"(a), "l"(b));
}
__device__ __forceinline__ void unpack2(unsigned long long v, float& lo, float& hi) {
    asm("mov.b64 {%0, %1}, %2;" : "=f"(lo), "=f"(hi) : "l"(v));
}

// ---------------- index dtype detection -----------------------------------
__global__ void detect_idx_kernel(const int* __restrict__ idx) {
    if (threadIdx.x == 0) {
        int allzero = 1;
        for (int i = 1; i < 128; i += 2)
            if (idx[i] != 0) { allzero = 0; break; }
        g_idx64 = allzero;
    }
}

__device__ __forceinline__ int load_idx(const int* idx, int pos, bool w64) {
    int v = w64 ? __ldg(&idx[2 * pos]) : __ldg(&idx[pos]);
    return min(max(v, 0), NN - 1);
}

// ---------------- CSR build -----------------------------------------------
__global__ void zero_count_kernel() {
    int i = blockIdx.x * blockDim.x + threadIdx.x;
    if (i < NN) g_count[i] = 0;
}

__global__ void hist_kernel(const int* __restrict__ idx, int E) {
    bool w64 = (g_idx64 != 0);
    int e = blockIdx.x * blockDim.x + threadIdx.x;
    if (e < E) {
        int d = load_idx(idx, E + e, w64);
        atomicAdd(&g_count[d], 1);
    }
}

// single-block exclusive scan (1024 threads, serial chunks) + cursor + rdeg
__global__ void scan_kernel(int n) {
    __shared__ int wsum[32];
    int t = threadIdx.x;
    int chunk = (n + 1023) >> 10;
    int b = t * chunk, e = min(b + chunk, n);
    int s = 0;
    for (int i = b; i < e; i++) s += g_count[i];
    int lane = t & 31, w = t >> 5;
    int v = s;
#pragma unroll
    for (int o = 1; o < 32; o <<= 1) {
        int u = __shfl_up_sync(0xffffffffu, v, o);
        if (lane >= o) v += u;
    }
    if (lane == 31) wsum[w] = v;
    __syncthreads();
    if (w == 0) {
        int x2 = wsum[lane];
#pragma unroll
        for (int o = 1; o < 32; o <<= 1) {
            int u = __shfl_up_sync(0xffffffffu, x2, o);
            if (lane >= o) x2 += u;
        }
        wsum[lane] = x2;
    }
    __syncthreads();
    int off = v - s + (w > 0 ? wsum[w - 1] : 0);
    for (int i = b; i < e; i++) {
        int c = g_count[i];
        g_offs[i] = off;
        g_cursor[i] = off;
        g_rdeg[i] = 1.0f / (float)max(c, 1);
        off += c;
    }
    if (t == 1023 && e == n) g_offs[n] = off;
}

__global__ void fill_kernel(const int* __restrict__ idx, int E) {
    bool w64 = (g_idx64 != 0);
    int e = blockIdx.x * blockDim.x + threadIdx.x;
    if (e < E) {
        int s = load_idx(idx, e, w64);
        int d = load_idx(idx, E + e, w64);
        int pos = atomicAdd(&g_cursor[d], 1);
        g_eidx[pos] = s;
    }
}

// ---------------- gather mean (warp per node, 128-wide rows) ---------------
__global__ void gather_mean_kernel(int featSel, const float* __restrict__ featExt,
                                   int outSel) {
    const float* feat = bufsel(featSel, featExt);
    float* out = bufsel(outSel, nullptr);
    int warp = (blockIdx.x * blockDim.x + threadIdx.x) >> 5;
    if (warp >= NN) return;
    int lane = threadIdx.x & 31;
    int start = g_offs[warp];
    int cnt = g_count[warp];
    float4 acc = make_float4(0.f, 0.f, 0.f, 0.f);
    int j = 0;
    for (; j + 2 <= cnt; j += 2) {
        int s0 = __ldg(&g_eidx[start + j]);
        int s1 = __ldg(&g_eidx[start + j + 1]);
        float4 v0 = *reinterpret_cast<const float4*>(feat + (size_t)s0 * 128 + lane * 4);
        float4 v1 = *reinterpret_cast<const float4*>(feat + (size_t)s1 * 128 + lane * 4);
        acc.x += v0.x + v1.x; acc.y += v0.y + v1.y;
        acc.z += v0.z + v1.z; acc.w += v0.w + v1.w;
    }
    if (j < cnt) {
        int s0 = __ldg(&g_eidx[start + j]);
        float4 v0 = *reinterpret_cast<const float4*>(feat + (size_t)s0 * 128 + lane * 4);
        acc.x += v0.x; acc.y += v0.y; acc.z += v0.z; acc.w += v0.w;
    }
    float r = g_rdeg[warp];
    acc.x *= r; acc.y *= r; acc.z *= r; acc.w *= r;
    *reinterpret_cast<float4*>(out + (size_t)warp * 128 + lane * 4) = acc;
}

// ---------------- GEMM: C[M,NTOT] = A @ B^T (+mean)(+bias)(+relu) ---------
// DUAL:  K=256 concat: k<128 -> A0(mean1) x B0; k>=128 -> A1(x) x B1
// MEANADD: epilogue adds g_msg2[m, n] (already a mean)
template <bool DUAL, bool RELU, bool MEANADD, int NTOT, int KTOT>
__global__ __launch_bounds__(256, 2)
void gemm_kernel(int aSel, const float* __restrict__ Aext,
                 const float* __restrict__ A1,
                 const float* __restrict__ B0w, const float* __restrict__ B1w,
                 const float* __restrict__ bias,
                 int cSel, float* __restrict__ Cext, int M) {
    constexpr int BM = 128, BN = 64, BK = 16;
    constexpr int LDA = DUAL ? 128 : KTOT;
    constexpr int LDB = DUAL ? 128 : KTOT;
    __shared__ __align__(16) float As[BK][BM];
    __shared__ __align__(16) float Bs[BK][BN];

    const float* A0 = bufsel(aSel, Aext);
    float* C = bufsel(cSel, Cext);

    int tid = threadIdx.x;
    int mBase = blockIdx.y * BM;
    int nBase = blockIdx.x * BN;

    unsigned long long acc[4][4];
#pragma unroll
    for (int i = 0; i < 4; i++)
#pragma unroll
        for (int j = 0; j < 4; j++) acc[i][j] = 0ULL;

    int tx = tid & 15;   // N dim (16 x 4)
    int ty = tid >> 4;   // M dim (16 x 8-rows as 4 f32x2 pairs)

    for (int kk = 0; kk < KTOT; kk += BK) {
        const float* Ap = (DUAL && kk >= 128) ? A1 : A0;
        int ko = DUAL ? (kk & 127) : kk;
#pragma unroll
        for (int i = 0; i < 2; i++) {
            int l = tid + i * 256;
            int r = l >> 2;
            int kc = (l & 3) << 2;
            int m = min(mBase + r, M - 1);
            float4 v = *reinterpret_cast<const float4*>(Ap + (size_t)m * LDA + ko + kc);
            As[kc + 0][r] = v.x; As[kc + 1][r] = v.y;
            As[kc + 2][r] = v.z; As[kc + 3][r] = v.w;
        }
        {
            const float* Bp = (DUAL && kk >= 128) ? B1w : B0w;
            int n = tid >> 2;
            int kc = (tid & 3) << 2;
            float4 w = *reinterpret_cast<const float4*>(Bp + (size_t)(nBase + n) * LDB + ko + kc);
            Bs[kc + 0][n] = w.x; Bs[kc + 1][n] = w.y;
            Bs[kc + 2][n] = w.z; Bs[kc + 3][n] = w.w;
        }
        __syncthreads();

#pragma unroll
        for (int k = 0; k < BK; k++) {
            const ulonglong2* ap = reinterpret_cast<const ulonglong2*>(&As[k][ty * 8]);
            ulonglong2 u0 = ap[0], u1 = ap[1];
            unsigned long long av0 = u0.x, av1 = u0.y, av2 = u1.x, av3 = u1.y;
            float4 b4 = *reinterpret_cast<const float4*>(&Bs[k][tx * 4]);
            unsigned long long bp0 = pack2(b4.x), bp1 = pack2(b4.y);
            unsigned long long bp2 = pack2(b4.z), bp3 = pack2(b4.w);
            ffma2(acc[0][0], av0, bp0); ffma2(acc[0][1], av0, bp1);
            ffma2(acc[0][2], av0, bp2); ffma2(acc[0][3], av0, bp3);
            ffma2(acc[1][0], av1, bp0); ffma2(acc[1][1], av1, bp1);
            ffma2(acc[1][2], av1, bp2); ffma2(acc[1][3], av1, bp3);
            ffma2(acc[2][0], av2, bp0); ffma2(acc[2][1], av2, bp1);
            ffma2(acc[2][2], av2, bp2); ffma2(acc[2][3], av2, bp3);
            ffma2(acc[3][0], av3, bp0); ffma2(acc[3][1], av3, bp1);
            ffma2(acc[3][2], av3, bp2); ffma2(acc[3][3], av3, bp3);
        }
        __syncthreads();
    }

    // ---- epilogue
    int m0 = mBase + ty * 8;
    int n0 = nBase + tx * 4;
    float4 b4 = make_float4(0.f, 0.f, 0.f, 0.f);
    if (bias != nullptr) b4 = *reinterpret_cast<const float4*>(bias + n0);

#pragma unroll
    for (int i = 0; i < 4; i++) {
        int r0 = m0 + 2 * i, r1 = r0 + 1;
        float lo[4], hi[4];
#pragma unroll
        for (int j = 0; j < 4; j++) unpack2(acc[i][j], lo[j], hi[j]);
        float4 vlo = make_float4(lo[0] + b4.x, lo[1] + b4.y, lo[2] + b4.z, lo[3] + b4.w);
        float4 vhi = make_float4(hi[0] + b4.x, hi[1] + b4.y, hi[2] + b4.z, hi[3] + b4.w);
        if (MEANADD) {
            if (r0 < M) {
                float4 m4 = *reinterpret_cast<const float4*>(g_msg2 + (size_t)r0 * NTOT + n0);
                vlo.x += m4.x; vlo.y += m4.y; vlo.z += m4.z; vlo.w += m4.w;
            }
            if (r1 < M) {
                float4 m4 = *reinterpret_cast<const float4*>(g_msg2 + (size_t)r1 * NTOT + n0);
                vhi.x += m4.x; vhi.y += m4.y; vhi.z += m4.z; vhi.w += m4.w;
            }
        }
        if (RELU) {
            vlo.x = fmaxf(vlo.x, 0.f); vlo.y = fmaxf(vlo.y, 0.f);
            vlo.z = fmaxf(vlo.z, 0.f); vlo.w = fmaxf(vlo.w, 0.f);
            vhi.x = fmaxf(vhi.x, 0.f); vhi.y = fmaxf(vhi.y, 0.f);
            vhi.z = fmaxf(vhi.z, 0.f); vhi.w = fmaxf(vhi.w, 0.f);
        }
        if (r0 < M) *reinterpret_cast<float4*>(C + (size_t)r0 * NTOT + n0) = vlo;
        if (r1 < M) *reinterpret_cast<float4*>(C + (size_t)r1 * NTOT + n0) = vhi;
    }
}

// ---------------- launch --------------------------------------------------
extern "C" void kernel_launch(void* const* d_in, const int* in_sizes, int n_in,
                              void* d_out, int out_size) {
    const float* x   = (const float*)d_in[0];
    const int* ei    = (const int*)d_in[1];   // int32 or int64, auto-detected
    const float* W1l = (const float*)d_in[3];
    const float* W1r = (const float*)d_in[4];
    const float* b1  = (const float*)d_in[5];
    const float* W2l = (const float*)d_in[6];
    const float* W2r = (const float*)d_in[7];
    const float* b2  = (const float*)d_in[8];
    float* out       = (float*)d_out;

    int M = in_sizes[0] / INC;        // 100000
    int E = in_sizes[1] / 2;          // 1600000
    if (E > EE) E = EE;

    int mTiles = (M + 127) / 128;
    int eBlocks = (E + 255) / 256;

    // 0) index dtype
    detect_idx_kernel<<<1, 32>>>(ei);

    // 1) CSR build (shared by both layers)
    zero_count_kernel<<<(NN + 255) / 256, 256>>>();
    hist_kernel<<<eBlocks, 256>>>(ei, E);
    scan_kernel<<<1, 1024>>>(M);
    fill_kernel<<<eBlocks, 256>>>(ei, E);

    // 2) mean1 = mean_{j->i} x_j
    gather_mean_kernel<<<(NN * 32 + 255) / 256, 256>>>(0, x, 1);

    // 3) h = relu( mean1 @ W1l^T + x @ W1r^T + b1 )
    gemm_kernel<true, true, false, HIDC, 256><<<dim3(HIDC / 64, mTiles), 256>>>(
        1, nullptr, x, W1l, W1r, b1, 2, nullptr, M);

    // 4) p = h @ W2l^T  (project before aggregate: 128-wide gather)
    gemm_kernel<false, false, false, OUTC, HIDC><<<dim3(OUTC / 64, mTiles), 256>>>(
        2, nullptr, nullptr, W2l, nullptr, nullptr, 3, nullptr, M);

    // 5) mean2 = mean_{j->i} p_j
    gather_mean_kernel<<<(NN * 32 + 255) / 256, 256>>>(3, nullptr, 4);

    // 6) out = mean2 + h @ W2r^T + b2
    gemm_kernel<false, false, true, OUTC, HIDC><<<dim3(OUTC / 64, mTiles), 256>>>(
        2, nullptr, nullptr, W2r, nullptr, b2, 0, out, M);
}

// round 13
// speedup vs baseline: 1.8884x; 1.8656x over previous
#include <cuda_runtime.h>
#include <cstdint>

#define NN 100000
#define EE 1700000
#define INC 128
#define HIDC 256
#define OUTC 128
#define SCANB 1024
#define NBLK ((NN + SCANB - 1) / SCANB)   // 98

// ---------------- scratch (device globals; no allocation allowed) ----------
__device__ float g_msg1[(size_t)NN * INC];
__device__ float g_rdeg[NN];
__device__ float g_h[(size_t)NN * HIDC];
__device__ float g_p[(size_t)NN * OUTC];
__device__ float g_msg2[(size_t)NN * OUTC];
__device__ int   g_count[NN];
__device__ int   g_offs[NN + 1];
__device__ int   g_cursor[NN];
__device__ int   g_eidx[EE];
__device__ int   g_bsum[128];
__device__ int   g_bpre[128];
__device__ int   g_idx64;

__device__ __forceinline__ float* bufsel(int s, const float* ext) {
    switch (s) {
        case 1: return g_msg1;
        case 2: return g_h;
        case 3: return g_p;
        case 4: return g_msg2;
        default: return const_cast<float*>(ext);
    }
}

// ---------------- f32x2 helpers -------------------------------------------
__device__ __forceinline__ unsigned long long pack2(float f) {
    unsigned long long r;
    asm("mov.b64 %0, {%1, %1};" : "=l"(r) : "f"(f));
    return r;
}
__device__ __forceinline__ void ffma2(unsigned long long& d, unsigned long long a,
                                      unsigned long long b) {
    asm("fma.rn.f32x2 %0, %1, %2, %0;" : "+l"(d) : "l"(a), "l"(b));
}
__device__ __forceinline__ void unpack2(unsigned long long v, float& lo, float& hi) {
    asm("mov.b64 {%0, %1}, %2;" : "=f"(lo), "=f"(hi) : "l"(v));
}

// ---------------- index dtype detection -----------------------------------
__global__ void detect_idx_kernel(const int* __restrict__ idx) {
    if (threadIdx.x == 0) {
        int allzero = 1;
        for (int i = 1; i < 128; i += 2)
            if (idx[i] != 0) { allzero = 0; break; }
        g_idx64 = allzero;
    }
}

__device__ __forceinline__ int load_idx(const int* idx, int pos, bool w64) {
    int v = w64 ? __ldg(&idx[2 * pos]) : __ldg(&idx[pos]);
    return min(max(v, 0), NN - 1);
}

// ---------------- CSR build -----------------------------------------------
__global__ void zero_count_kernel() {
    int i = blockIdx.x * blockDim.x + threadIdx.x;
    if (i < NN) g_count[i] = 0;
}

__global__ void hist_kernel(const int* __restrict__ idx, int E) {
    bool w64 = (g_idx64 != 0);
    int e = blockIdx.x * blockDim.x + threadIdx.x;
    if (e < E) {
        int d = load_idx(idx, E + e, w64);
        atomicAdd(&g_count[d], 1);
    }
}

// Phase A: per-block (1024-wide) exclusive scan; local prefix -> g_offs,
// block total -> g_bsum.
__global__ void scanA_kernel(int n) {
    __shared__ int wsum[32];
    int t = threadIdx.x;
    int i = blockIdx.x * SCANB + t;
    int c = (i < n) ? g_count[i] : 0;
    int lane = t & 31, w = t >> 5;
    int v = c;
#pragma unroll
    for (int o = 1; o < 32; o <<= 1) {
        int u = __shfl_up_sync(0xffffffffu, v, o);
        if (lane >= o) v += u;
    }
    if (lane == 31) wsum[w] = v;
    __syncthreads();
    if (w == 0) {
        int x2 = wsum[lane];
#pragma unroll
        for (int o = 1; o < 32; o <<= 1) {
            int u = __shfl_up_sync(0xffffffffu, x2, o);
            if (lane >= o) x2 += u;
        }
        wsum[lane] = x2;
    }
    __syncthreads();
    int incl = v + (w > 0 ? wsum[w - 1] : 0);
    if (i < n) g_offs[i] = incl - c;          // block-local exclusive prefix
    if (t == SCANB - 1) g_bsum[blockIdx.x] = incl;
}

// Phase B: one block scans the (<=128) block totals -> exclusive prefixes.
__global__ void scanB_kernel(int nb) {
    __shared__ int wsum[4];
    int t = threadIdx.x;                       // 128 threads
    int lane = t & 31, w = t >> 5;
    int c = (t < nb) ? g_bsum[t] : 0;
    int v = c;
#pragma unroll
    for (int o = 1; o < 32; o <<= 1) {
        int u = __shfl_up_sync(0xffffffffu, v, o);
        if (lane >= o) v += u;
    }
    if (lane == 31) wsum[w] = v;
    __syncthreads();
    if (t == 0) {
        int a = 0;
        for (int k = 0; k < 4; k++) { int s = wsum[k]; wsum[k] = a; a += s; }
    }
    __syncthreads();
    g_bpre[t] = v - c + wsum[w];               // exclusive prefix
}

// Phase C: add block prefix; emit offs/cursor/rdeg (+ total sentinel).
__global__ void scanC_kernel(int n) {
    int i = blockIdx.x * blockDim.x + threadIdx.x;
    if (i < n) {
        int c = g_count[i];
        int off = g_offs[i] + g_bpre[i >> 10];
        g_offs[i] = off;
        g_cursor[i] = off;
        g_rdeg[i] = 1.0f / (float)max(c, 1);
        if (i == n - 1) g_offs[n] = off + c;
    }
}

__global__ void fill_kernel(const int* __restrict__ idx, int E) {
    bool w64 = (g_idx64 != 0);
    int e = blockIdx.x * blockDim.x + threadIdx.x;
    if (e < E) {
        int s = load_idx(idx, e, w64);
        int d = load_idx(idx, E + e, w64);
        int pos = atomicAdd(&g_cursor[d], 1);
        g_eidx[pos] = s;
    }
}

// ---------------- gather mean (warp per node, 128-wide rows, unroll 4) -----
__global__ void gather_mean_kernel(int featSel, const float* __restrict__ featExt,
                                   int outSel) {
    const float* feat = bufsel(featSel, featExt);
    float* out = bufsel(outSel, nullptr);
    int warp = (blockIdx.x * blockDim.x + threadIdx.x) >> 5;
    if (warp >= NN) return;
    int lane = threadIdx.x & 31;
    int start = g_offs[warp];
    int cnt = g_count[warp];
    float4 acc = make_float4(0.f, 0.f, 0.f, 0.f);
    int j = 0;
    for (; j + 4 <= cnt; j += 4) {
        int s0 = __ldg(&g_eidx[start + j]);
        int s1 = __ldg(&g_eidx[start + j + 1]);
        int s2 = __ldg(&g_eidx[start + j + 2]);
        int s3 = __ldg(&g_eidx[start + j + 3]);
        float4 v0 = *reinterpret_cast<const float4*>(feat + (size_t)s0 * 128 + lane * 4);
        float4 v1 = *reinterpret_cast<const float4*>(feat + (size_t)s1 * 128 + lane * 4);
        float4 v2 = *reinterpret_cast<const float4*>(feat + (size_t)s2 * 128 + lane * 4);
        float4 v3 = *reinterpret_cast<const float4*>(feat + (size_t)s3 * 128 + lane * 4);
        acc.x += (v0.x + v1.x) + (v2.x + v3.x);
        acc.y += (v0.y + v1.y) + (v2.y + v3.y);
        acc.z += (v0.z + v1.z) + (v2.z + v3.z);
        acc.w += (v0.w + v1.w) + (v2.w + v3.w);
    }
    for (; j < cnt; j++) {
        int s0 = __ldg(&g_eidx[start + j]);
        float4 v0 = *reinterpret_cast<const float4*>(feat + (size_t)s0 * 128 + lane * 4);
        acc.x += v0.x; acc.y += v0.y; acc.z += v0.z; acc.w += v0.w;
    }
    float r = g_rdeg[warp];
    acc.x *= r; acc.y *= r; acc.z *= r; acc.w *= r;
    *reinterpret_cast<float4*>(out + (size_t)warp * 128 + lane * 4) = acc;
}

// ---------------- GEMM: C[M,NTOT] = A @ B^T (+mean)(+bias)(+relu) ---------
template <bool DUAL, bool RELU, bool MEANADD, int NTOT, int KTOT>
__global__ __launch_bounds__(256, 2)
void gemm_kernel(int aSel, const float* __restrict__ Aext,
                 const float* __restrict__ A1,
                 const float* __restrict__ B0w, const float* __restrict__ B1w,
                 const float* __restrict__ bias,
                 int cSel, float* __restrict__ Cext, int M) {
    constexpr int BM = 128, BN = 64, BK = 16;
    constexpr int LDA = DUAL ? 128 : KTOT;
    constexpr int LDB = DUAL ? 128 : KTOT;
    __shared__ __align__(16) float As[BK][BM];
    __shared__ __align__(16) float Bs[BK][BN];

    const float* A0 = bufsel(aSel, Aext);
    float* C = bufsel(cSel, Cext);

    int tid = threadIdx.x;
    int mBase = blockIdx.y * BM;
    int nBase = blockIdx.x * BN;

    unsigned long long acc[4][4];
#pragma unroll
    for (int i = 0; i < 4; i++)
#pragma unroll
        for (int j = 0; j < 4; j++) acc[i][j] = 0ULL;

    int tx = tid & 15;
    int ty = tid >> 4;

    for (int kk = 0; kk < KTOT; kk += BK) {
        const float* Ap = (DUAL && kk >= 128) ? A1 : A0;
        int ko = DUAL ? (kk & 127) : kk;
#pragma unroll
        for (int i = 0; i < 2; i++) {
            int l = tid + i * 256;
            int r = l >> 2;
            int kc = (l & 3) << 2;
            int m = min(mBase + r, M - 1);
            float4 v = *reinterpret_cast<const float4*>(Ap + (size_t)m * LDA + ko + kc);
            As[kc + 0][r] = v.x; As[kc + 1][r] = v.y;
            As[kc + 2][r] = v.z; As[kc + 3][r] = v.w;
        }
        {
            const float* Bp = (DUAL && kk >= 128) ? B1w : B0w;
            int n = tid >> 2;
            int kc = (tid & 3) << 2;
            float4 w = *reinterpret_cast<const float4*>(Bp + (size_t)(nBase + n) * LDB + ko + kc);
            Bs[kc + 0][n] = w.x; Bs[kc + 1][n] = w.y;
            Bs[kc + 2][n] = w.z; Bs[kc + 3][n] = w.w;
        }
        __syncthreads();

#pragma unroll
        for (int k = 0; k < BK; k++) {
            const ulonglong2* ap = reinterpret_cast<const ulonglong2*>(&As[k][ty * 8]);
            ulonglong2 u0 = ap[0], u1 = ap[1];
            unsigned long long av0 = u0.x, av1 = u0.y, av2 = u1.x, av3 = u1.y;
            float4 b4 = *reinterpret_cast<const float4*>(&Bs[k][tx * 4]);
            unsigned long long bp0 = pack2(b4.x), bp1 = pack2(b4.y);
            unsigned long long bp2 = pack2(b4.z), bp3 = pack2(b4.w);
            ffma2(acc[0][0], av0, bp0); ffma2(acc[0][1], av0, bp1);
            ffma2(acc[0][2], av0, bp2); ffma2(acc[0][3], av0, bp3);
            ffma2(acc[1][0], av1, bp0); ffma2(acc[1][1], av1, bp1);
            ffma2(acc[1][2], av1, bp2); ffma2(acc[1][3], av1, bp3);
            ffma2(acc[2][0], av2, bp0); ffma2(acc[2][1], av2, bp1);
            ffma2(acc[2][2], av2, bp2); ffma2(acc[2][3], av2, bp3);
            ffma2(acc[3][0], av3, bp0); ffma2(acc[3][1], av3, bp1);
            ffma2(acc[3][2], av3, bp2); ffma2(acc[3][3], av3, bp3);
        }
        __syncthreads();
    }

    int m0 = mBase + ty * 8;
    int n0 = nBase + tx * 4;
    float4 b4 = make_float4(0.f, 0.f, 0.f, 0.f);
    if (bias != nullptr) b4 = *reinterpret_cast<const float4*>(bias + n0);

#pragma unroll
    for (int i = 0; i < 4; i++) {
        int r0 = m0 + 2 * i, r1 = r0 + 1;
        float lo[4], hi[4];
#pragma unroll
        for (int j = 0; j < 4; j++) unpack2(acc[i][j], lo[j], hi[j]);
        float4 vlo = make_float4(lo[0] + b4.x, lo[1] + b4.y, lo[2] + b4.z, lo[3] + b4.w);
        float4 vhi = make_float4(hi[0] + b4.x, hi[1] + b4.y, hi[2] + b4.z, hi[3] + b4.w);
        if (MEANADD) {
            if (r0 < M) {
                float4 m4 = *reinterpret_cast<const float4*>(g_msg2 + (size_t)r0 * NTOT + n0);
                vlo.x += m4.x; vlo.y += m4.y; vlo.z += m4.z; vlo.w += m4.w;
            }
            if (r1 < M) {
                float4 m4 = *reinterpret_cast<const float4*>(g_msg2 + (size_t)r1 * NTOT + n0);
                vhi.x += m4.x; vhi.y += m4.y; vhi.z += m4.z; vhi.w += m4.w;
            }
        }
        if (RELU) {
            vlo.x = fmaxf(vlo.x, 0.f); vlo.y = fmaxf(vlo.y, 0.f);
            vlo.z = fmaxf(vlo.z, 0.f); vlo.w = fmaxf(vlo.w, 0.f);
            vhi.x = fmaxf(vhi.x, 0.f); vhi.y = fmaxf(vhi.y, 0.f);
            vhi.z = fmaxf(vhi.z, 0.f); vhi.w = fmaxf(vhi.w, 0.f);
        }
        if (r0 < M) *reinterpret_cast<float4*>(C + (size_t)r0 * NTOT + n0) = vlo;
        if (r1 < M) *reinterpret_cast<float4*>(C + (size_t)r1 * NTOT + n0) = vhi;
    }
}

// ---------------- launch --------------------------------------------------
extern "C" void kernel_launch(void* const* d_in, const int* in_sizes, int n_in,
                              void* d_out, int out_size) {
    const float* x   = (const float*)d_in[0];
    const int* ei    = (const int*)d_in[1];
    const float* W1l = (const float*)d_in[3];
    const float* W1r = (const float*)d_in[4];
    const float* b1  = (const float*)d_in[5];
    const float* W2l = (const float*)d_in[6];
    const float* W2r = (const float*)d_in[7];
    const float* b2  = (const float*)d_in[8];
    float* out       = (float*)d_out;

    int M = in_sizes[0] / INC;        // 100000
    int E = in_sizes[1] / 2;          // 1600000
    if (E > EE) E = EE;

    int mTiles = (M + 127) / 128;
    int eBlocks = (E + 255) / 256;
    int nBlk = (M + SCANB - 1) / SCANB;

    detect_idx_kernel<<<1, 32>>>(ei);

    // CSR build (parallel 3-phase scan)
    zero_count_kernel<<<(NN + 255) / 256, 256>>>();
    hist_kernel<<<eBlocks, 256>>>(ei, E);
    scanA_kernel<<<nBlk, SCANB>>>(M);
    scanB_kernel<<<1, 128>>>(nBlk);
    scanC_kernel<<<(M + 255) / 256, 256>>>(M);
    fill_kernel<<<eBlocks, 256>>>(ei, E);

    // mean1 = mean_{j->i} x_j
    gather_mean_kernel<<<(NN * 32 + 255) / 256, 256>>>(0, x, 1);

    // h = relu( mean1 @ W1l^T + x @ W1r^T + b1 )
    gemm_kernel<true, true, false, HIDC, 256><<<dim3(HIDC / 64, mTiles), 256>>>(
        1, nullptr, x, W1l, W1r, b1, 2, nullptr, M);

    // p = h @ W2l^T
    gemm_kernel<false, false, false, OUTC, HIDC><<<dim3(OUTC / 64, mTiles), 256>>>(
        2, nullptr, nullptr, W2l, nullptr, nullptr, 3, nullptr, M);

    // mean2 = mean_{j->i} p_j
    gather_mean_kernel<<<(NN * 32 + 255) / 256, 256>>>(3, nullptr, 4);

    // out = mean2 + h @ W2r^T + b2
    gemm_kernel<false, false, true, OUTC, HIDC><<<dim3(OUTC / 64, mTiles), 256>>>(
        2, nullptr, nullptr, W2r, nullptr, b2, 0, out, M);
}